// round 4
// baseline (speedup 1.0000x reference)
#include <cuda_runtime.h>

// ---------------- problem constants ----------------
#define BATCH   128
#define DCH     128
#define HW      1024            // 32*32
#define NROWS   131072          // BATCH*HW
#define KCODE   256
#define TILE    128             // rows per GEMM CTA
#define NTILES  1024            // NROWS / TILE

// ---------------- output layout (concatenated reference tuple, fp32) -------
#define Q_OFF      0
#define IDX_OFF    16777216
#define COMMIT_OFF 16908288
#define CBL_OFF    16908289
#define NCB_OFF    16908290
#define CNT_OFF    16941058
#define NW_OFF     16941314

#define SCB_STRIDE 258

// ---------------- device scratch -------------------------------------------
__device__ int   g_idx[NROWS];
__device__ float g_cnorm[KCODE];
__device__ float g_losspart[NTILES];
__device__ float g_part[BATCH * KCODE * DCH];
__device__ float g_cntpart[BATCH * KCODE];

// ---------------- f32x2 helpers --------------------------------------------
__device__ __forceinline__ unsigned long long dup2(float x) {
    unsigned long long r;
    asm("mov.b64 %0, {%1, %1};" : "=l"(r) : "f"(x));
    return r;
}
__device__ __forceinline__ void ffma2(unsigned long long& d,
                                      unsigned long long a,
                                      unsigned long long b) {
    asm("fma.rn.f32x2 %0, %1, %2, %0;" : "+l"(d) : "l"(a), "l"(b));
}

// ---------------- kernel 1: codebook row norms (XLA-style reduce) ----------
__global__ void k_prep(const float* __restrict__ cb) {
    int w = threadIdx.x >> 5, lane = threadIdx.x & 31;
    for (int rr = 0; rr < 32; rr++) {
        int k = w * 32 + rr;
        // strided partial: c = lane, lane+32, lane+64, lane+96 (mul then add)
        float v0 = cb[k * DCH + lane];
        float s  = __fmul_rn(v0, v0);
#pragma unroll
        for (int j = 1; j < 4; j++) {
            float v = cb[k * DCH + j * 32 + lane];
            s = __fadd_rn(s, __fmul_rn(v, v));
        }
#pragma unroll
        for (int o = 16; o; o >>= 1)
            s = __fadd_rn(s, __shfl_xor_sync(0xffffffffu, s, o));
        if (lane == 0) g_cnorm[k] = s;
    }
}

// ---------------- kernel 2: fused distance GEMM + argmin + quantize + loss -
__global__ void __launch_bounds__(256, 1)
k_gemm(const float* __restrict__ z, const float* __restrict__ cb,
       float* __restrict__ out) {
    extern __shared__ float sm[];
    float* zt   = sm;                              // [128 c][128 n]
    float* scb  = sm + 16384;                      // [128 c][258]
    float* scn  = scb + 128 * SCB_STRIDE;          // [256]
    int*   sidx = (int*)(scn + 256);               // [128]
    __shared__ float red[8];
    __shared__ float szn[TILE];

    const int tid    = threadIdx.x;
    const int tileId = blockIdx.x;
    const int b      = tileId >> 3;
    const int hw0    = (tileId & 7) << 7;
    const int n0     = tileId * TILE;

    if (tid < 256) scn[tid] = g_cnorm[tid];

    {
        const float* zb = z + (b * DCH) * HW + hw0;
        for (int i = tid; i < TILE * DCH; i += 256) {
            int c = i >> 7, n = i & 127;
            zt[c * TILE + n] = zb[c * HW + n];
        }
    }
    for (int i = tid; i < KCODE * DCH; i += 256) {
        int k = i >> 7, c = i & 127;
        scb[c * SCB_STRIDE + k] = cb[i];
    }
    __syncthreads();

    // ---- znorm per row, replicating XLA warp-reduce:
    // 32 strided partials (c = lane + 32j, mul-then-add), butterfly tree.
    {
        const int w = tid >> 5, lane = tid & 31;
        for (int r = 0; r < 16; r++) {
            int n = w * 16 + r;
            float v0 = zt[lane * TILE + n];
            float a  = __fmul_rn(v0, v0);
#pragma unroll
            for (int j = 1; j < 4; j++) {
                float v = zt[(lane + 32 * j) * TILE + n];
                a = __fadd_rn(a, __fmul_rn(v, v));
            }
#pragma unroll
            for (int o = 16; o; o >>= 1)
                a = __fadd_rn(a, __shfl_xor_sync(0xffffffffu, a, o));
            if (lane == 0) szn[n] = a;
        }
    }
    __syncthreads();

    const int kg = tid & 15, ng = tid >> 4;

    unsigned long long acc[64];
#pragma unroll
    for (int i = 0; i < 64; i++) acc[i] = 0ull;

    const float* zrow = zt + ng * 8;
    const float* crow = scb + 2 * kg;

#pragma unroll 2
    for (int c = 0; c < DCH; c++) {
        float4 za  = *(const float4*)(zrow + c * TILE);
        float4 zb4 = *(const float4*)(zrow + c * TILE + 4);
        unsigned long long zd[8];
        zd[0] = dup2(za.x);  zd[1] = dup2(za.y);
        zd[2] = dup2(za.z);  zd[3] = dup2(za.w);
        zd[4] = dup2(zb4.x); zd[5] = dup2(zb4.y);
        zd[6] = dup2(zb4.z); zd[7] = dup2(zb4.w);
        unsigned long long cbp[8];
#pragma unroll
        for (int j = 0; j < 8; j++)
            cbp[j] = *(const unsigned long long*)(crow + c * SCB_STRIDE + 32 * j);
#pragma unroll
        for (int i = 0; i < 8; i++)
#pragma unroll
            for (int j = 0; j < 8; j++)
                ffma2(acc[i * 8 + j], zd[i], cbp[j]);
    }

    // ---- argmin with reference-rounded distances:
    // d = fl(fl(znorm - fl(2*dot)) + cnorm)
    float zn_i[8];
#pragma unroll
    for (int i = 0; i < 8; i++) zn_i[i] = szn[ng * 8 + i];

    float minv[8];
    int   mink[8];
#pragma unroll
    for (int i = 0; i < 8; i++) { minv[i] = 3.4e38f; mink[i] = 0; }
#pragma unroll
    for (int j = 0; j < 8; j++) {
        int k0 = 2 * kg + 32 * j;
        float cn0 = scn[k0], cn1 = scn[k0 + 1];
#pragma unroll
        for (int i = 0; i < 8; i++) {
            unsigned long long v = acc[i * 8 + j];
            float lo = __uint_as_float((unsigned)v);
            float hi = __uint_as_float((unsigned)(v >> 32));
            float d0 = __fadd_rn(__fadd_rn(zn_i[i], -__fmul_rn(2.f, lo)), cn0);
            float d1 = __fadd_rn(__fadd_rn(zn_i[i], -__fmul_rn(2.f, hi)), cn1);
            if (d0 < minv[i]) { minv[i] = d0; mink[i] = k0; }
            if (d1 < minv[i]) { minv[i] = d1; mink[i] = k0 + 1; }
        }
    }
#pragma unroll
    for (int i = 0; i < 8; i++) {
#pragma unroll
        for (int off = 8; off; off >>= 1) {
            float ov = __shfl_xor_sync(0xffffffffu, minv[i], off);
            int   ok = __shfl_xor_sync(0xffffffffu, mink[i], off);
            if (ov < minv[i] || (ov == minv[i] && ok < mink[i])) {
                minv[i] = ov; mink[i] = ok;
            }
        }
    }
    if (kg == 0) {
#pragma unroll
        for (int i = 0; i < 8; i++) {
            int n = ng * 8 + i;
            sidx[n] = mink[i];
            g_idx[n0 + n] = mink[i];
            out[IDX_OFF + n0 + n] = (float)mink[i];
        }
    }
    __syncthreads();

    // ---- fused quantize (straight-through) + loss ----
    float lsum = 0.f;
    float* outq = out + Q_OFF + (b * DCH) * HW + hw0;
#pragma unroll 4
    for (int it = 0; it < 64; it++) {
        int e = it * 256 + tid;
        int c = e >> 7, n = e & 127;
        int k = sidx[n];
        float zv = zt[c * TILE + n];
        float q  = scb[c * SCB_STRIDE + k];
        float d  = __fadd_rn(q, -zv);                 // fl(q - z)
        outq[c * HW + n] = __fadd_rn(zv, d);          // fl(z + fl(q - z))
        lsum += d * d;
    }
#pragma unroll
    for (int off = 16; off; off >>= 1)
        lsum += __shfl_xor_sync(0xffffffffu, lsum, off);
    int w = tid >> 5;
    if ((tid & 31) == 0) red[w] = lsum;
    __syncthreads();
    if (tid == 0) {
        float t = 0.f;
        for (int i = 0; i < 8; i++) t += red[i];
        g_losspart[blockIdx.x] = t;
    }
}

// ---------------- kernel 3: per-batch enc_batch / enc_sum partials --------
__global__ void __launch_bounds__(512, 1)
k_encbatch(const float* __restrict__ z) {
    extern __shared__ float sm[];
    float* sacc  = sm;                         // [256][128]
    int*   ssidx = (int*)(sm + KCODE * DCH);   // [1024]
    int*   scnt  = ssidx + HW;                 // [256]
    const int tid = threadIdx.x, b = blockIdx.x;

    for (int i = tid; i < KCODE * DCH; i += 512) sacc[i] = 0.f;
    if (tid < 256) scnt[tid] = 0;
    for (int i = tid; i < HW; i += 512) ssidx[i] = g_idx[b * HW + i];
    __syncthreads();

    const int ks = tid >> 7, c = tid & 127;
    const float* zb = z + (b * DCH + c) * HW;
    for (int row = 0; row < HW; row++) {
        int k = ssidx[row];
        if ((k & 3) == ks) {
            sacc[k * DCH + c] += zb[row];
            if (c == 0) scnt[k]++;
        }
    }
    __syncthreads();
    for (int i = tid; i < KCODE * DCH; i += 512)
        g_part[b * (KCODE * DCH) + i] = sacc[i];
    if (tid < 256) g_cntpart[b * KCODE + tid] = (float)scnt[tid];
}

// ---------------- kernel 4: reduce partials -> new_weight -----------------
__global__ void k_reduceparts(const float* __restrict__ emaw,
                              float* __restrict__ out) {
    int k = blockIdx.x, c = threadIdx.x;
    float s = 0.f;
    const float* p = g_part + k * DCH + c;
#pragma unroll 8
    for (int b = 0; b < BATCH; b++) s += p[b * (KCODE * DCH)];
    int i = k * DCH + c;
    out[NW_OFF + i] = __fadd_rn(__fmul_rn(0.99f, emaw[i]), __fmul_rn(0.01f, s));
}

// ---------------- kernel 5: counts, losses, codebook normalization --------
__global__ void k_final(const float* __restrict__ emac, float* __restrict__ out) {
    __shared__ float snc[256], snorm[256], sred[256];
    __shared__ float s_n;
    const int t = threadIdx.x;

    float cs = 0.f;
    for (int b = 0; b < BATCH; b++) cs += g_cntpart[b * KCODE + t];
    float nc = __fadd_rn(__fmul_rn(0.99f, emac[t]), __fmul_rn(0.01f, cs));
    out[CNT_OFF + t] = nc;
    snc[t] = nc;

    float lp = 0.f;
    for (int i = t; i < NTILES; i += 256) lp += g_losspart[i];
    sred[t] = lp;
    __syncthreads();

    if (t == 0) {
        float n = 0.f;
        for (int i = 0; i < 256; i++) n += snc[i];
        s_n = n;
        float L = 0.f;
        for (int i = 0; i < 256; i++) L += sred[i];
        L /= 16777216.0f;
        out[COMMIT_OFF] = 0.25f * L;
        out[CBL_OFF]    = L;
    }
    __syncthreads();

    float n = s_n;
    snorm[t] = __fmul_rn(__fdiv_rn(__fadd_rn(snc[t], 1e-5f),
                                   __fadd_rn(n, 256.0f * 1e-5f)), n);
    __syncthreads();

    for (int i = t; i < KCODE * DCH; i += 256)
        out[NCB_OFF + i] = __fdiv_rn(out[NW_OFF + i], snorm[i >> 7]);
}

// ---------------- launch ---------------------------------------------------
extern "C" void kernel_launch(void* const* d_in, const int* in_sizes, int n_in,
                              void* d_out, int out_size) {
    const float* z    = (const float*)d_in[0];
    const float* cb   = (const float*)d_in[1];
    const float* emac = (const float*)d_in[2];
    const float* emaw = (const float*)d_in[3];
    float* out = (float*)d_out;

    const int GEMM_SMEM = (16384 + 128 * SCB_STRIDE + 256 + 128) * 4;
    const int ENC_SMEM  = (KCODE * DCH) * 4 + HW * 4 + KCODE * 4;
    cudaFuncSetAttribute(k_gemm, cudaFuncAttributeMaxDynamicSharedMemorySize,
                         GEMM_SMEM);
    cudaFuncSetAttribute(k_encbatch, cudaFuncAttributeMaxDynamicSharedMemorySize,
                         ENC_SMEM);

    k_prep<<<1, 256>>>(cb);
    k_gemm<<<NTILES, 256, GEMM_SMEM>>>(z, cb, out);
    k_encbatch<<<BATCH, 512, ENC_SMEM>>>(z);
    k_reduceparts<<<KCODE, DCH>>>(emaw, out);
    k_final<<<1, 256>>>(emac, out);
}

// round 7
// speedup vs baseline: 1.1861x; 1.1861x over previous
#include <cuda_runtime.h>

// ---------------- problem constants ----------------
#define BATCH   128
#define DCH     128
#define HW      1024
#define NROWS   131072
#define KCODE   256
#define TILE    128
#define NTILES  1024

// ---------------- output layout --------------------
#define Q_OFF      0
#define IDX_OFF    16777216
#define COMMIT_OFF 16908288
#define CBL_OFF    16908289
#define NCB_OFF    16908290
#define CNT_OFF    16941058
#define NW_OFF     16941314

#define SCB_STRIDE 258

// ---------------- device scratch -------------------
__device__ int   g_idx[NROWS];
__device__ float g_cnorm[KCODE];
__device__ float g_losspart[NTILES];
__device__ float g_part[BATCH * KCODE * DCH];
__device__ float g_part2[8 * KCODE * DCH];
__device__ float g_cntpart[BATCH * KCODE];
__device__ float g_snorm[KCODE];

// ---------------- f32x2 helpers --------------------
__device__ __forceinline__ unsigned long long dup2(float x) {
    unsigned long long r;
    asm("mov.b64 %0, {%1, %1};" : "=l"(r) : "f"(x));
    return r;
}
__device__ __forceinline__ void ffma2(unsigned long long& d,
                                      unsigned long long a,
                                      unsigned long long b) {
    asm("fma.rn.f32x2 %0, %1, %2, %0;" : "+l"(d) : "l"(a), "l"(b));
}

// ---------------- kernel 1: codebook row norms -----
__global__ void k_prep(const float* __restrict__ cb) {
    int w = threadIdx.x >> 5, lane = threadIdx.x & 31;
    for (int rr = 0; rr < 32; rr++) {
        int k = w * 32 + rr;
        float v0 = cb[k * DCH + lane];
        float s  = __fmul_rn(v0, v0);
#pragma unroll
        for (int j = 1; j < 4; j++) {
            float v = cb[k * DCH + j * 32 + lane];
            s = __fadd_rn(s, __fmul_rn(v, v));
        }
#pragma unroll
        for (int o = 16; o; o >>= 1)
            s = __fadd_rn(s, __shfl_xor_sync(0xffffffffu, s, o));
        if (lane == 0) g_cnorm[k] = s;
    }
}

// ---------------- kernel 2: fused GEMM + argmin + quantize + loss ----------
// 512 threads. kg = tid & 15 (16 k-groups of 16 codes as 8 f32x2 pairs),
// ng = tid >> 4 (32 n-groups of 4 rows). 32 u64 accumulators per thread.
__global__ void __launch_bounds__(512, 1)
k_gemm(const float* __restrict__ z, const float* __restrict__ cb,
       float* __restrict__ out) {
    extern __shared__ float sm[];
    float* zt   = sm;                              // [128 c][128 n]
    float* scb  = sm + 16384;                      // [128 c][258]
    float* scn  = scb + 128 * SCB_STRIDE;          // [256]
    int*   sidx = (int*)(scn + 256);               // [128]
    __shared__ float red[16];
    __shared__ float szn[TILE];

    const int tid    = threadIdx.x;
    const int tileId = blockIdx.x;
    const int b      = tileId >> 3;
    const int hw0    = (tileId & 7) << 7;
    const int n0     = tileId * TILE;

    if (tid < 256) scn[tid] = g_cnorm[tid];

    {
        const float* zb = z + (b * DCH) * HW + hw0;
        for (int i = tid; i < TILE * DCH; i += 512) {
            int c = i >> 7, n = i & 127;
            zt[c * TILE + n] = zb[c * HW + n];
        }
    }
    for (int i = tid; i < KCODE * DCH; i += 512) {
        int k = i >> 7, c = i & 127;
        scb[c * SCB_STRIDE + k] = cb[i];
    }
    __syncthreads();

    // znorm per row: 32 strided partials (c = lane+32j, mul-then-add),
    // butterfly tree — identical rounding to the passing R4 version.
    {
        const int w = tid >> 5, lane = tid & 31;
        for (int r = 0; r < 8; r++) {
            int n = w * 8 + r;
            float v0 = zt[lane * TILE + n];
            float a  = __fmul_rn(v0, v0);
#pragma unroll
            for (int j = 1; j < 4; j++) {
                float v = zt[(lane + 32 * j) * TILE + n];
                a = __fadd_rn(a, __fmul_rn(v, v));
            }
#pragma unroll
            for (int o = 16; o; o >>= 1)
                a = __fadd_rn(a, __shfl_xor_sync(0xffffffffu, a, o));
            if (lane == 0) szn[n] = a;
        }
    }
    __syncthreads();

    const int kg = tid & 15, ng = tid >> 4;

    unsigned long long acc[32];
#pragma unroll
    for (int i = 0; i < 32; i++) acc[i] = 0ull;

    const float* zrow = zt + ng * 4;
    const float* crow = scb + 2 * kg;

#pragma unroll 2
    for (int c = 0; c < DCH; c++) {
        float4 za = *(const float4*)(zrow + c * TILE);
        unsigned long long zd[4];
        zd[0] = dup2(za.x); zd[1] = dup2(za.y);
        zd[2] = dup2(za.z); zd[3] = dup2(za.w);
        unsigned long long cbp[8];
#pragma unroll
        for (int j = 0; j < 8; j++)
            cbp[j] = *(const unsigned long long*)(crow + c * SCB_STRIDE + 32 * j);
#pragma unroll
        for (int i = 0; i < 4; i++)
#pragma unroll
            for (int j = 0; j < 8; j++)
                ffma2(acc[i * 8 + j], zd[i], cbp[j]);
    }

    // argmin with reference-rounded distances: fl(fl(zn - fl(2*dot)) + cn)
    float zn_i[4];
#pragma unroll
    for (int i = 0; i < 4; i++) zn_i[i] = szn[ng * 4 + i];

    float minv[4];
    int   mink[4];
#pragma unroll
    for (int i = 0; i < 4; i++) { minv[i] = 3.4e38f; mink[i] = 0; }
#pragma unroll
    for (int j = 0; j < 8; j++) {
        int k0 = 2 * kg + 32 * j;
        float cn0 = scn[k0], cn1 = scn[k0 + 1];
#pragma unroll
        for (int i = 0; i < 4; i++) {
            unsigned long long v = acc[i * 8 + j];
            float lo = __uint_as_float((unsigned)v);
            float hi = __uint_as_float((unsigned)(v >> 32));
            float d0 = __fadd_rn(__fadd_rn(zn_i[i], -__fmul_rn(2.f, lo)), cn0);
            float d1 = __fadd_rn(__fadd_rn(zn_i[i], -__fmul_rn(2.f, hi)), cn1);
            if (d0 < minv[i]) { minv[i] = d0; mink[i] = k0; }
            if (d1 < minv[i]) { minv[i] = d1; mink[i] = k0 + 1; }
        }
    }
#pragma unroll
    for (int i = 0; i < 4; i++) {
#pragma unroll
        for (int off = 8; off; off >>= 1) {
            float ov = __shfl_xor_sync(0xffffffffu, minv[i], off);
            int   ok = __shfl_xor_sync(0xffffffffu, mink[i], off);
            if (ov < minv[i] || (ov == minv[i] && ok < mink[i])) {
                minv[i] = ov; mink[i] = ok;
            }
        }
    }
    if (kg == 0) {
#pragma unroll
        for (int i = 0; i < 4; i++) {
            int n = ng * 4 + i;
            sidx[n] = mink[i];
            g_idx[n0 + n] = mink[i];
            out[IDX_OFF + n0 + n] = (float)mink[i];
        }
    }
    __syncthreads();

    // fused quantize (straight-through) + loss
    float lsum = 0.f;
    float* outq = out + Q_OFF + (b * DCH) * HW + hw0;
#pragma unroll 4
    for (int it = 0; it < 32; it++) {
        int e = it * 512 + tid;
        int c = e >> 7, n = e & 127;
        int k = sidx[n];
        float zv = zt[c * TILE + n];
        float q  = scb[c * SCB_STRIDE + k];
        float d  = __fadd_rn(q, -zv);
        outq[c * HW + n] = __fadd_rn(zv, d);
        lsum += d * d;
    }
#pragma unroll
    for (int off = 16; off; off >>= 1)
        lsum += __shfl_xor_sync(0xffffffffu, lsum, off);
    int w = tid >> 5;
    if ((tid & 31) == 0) red[w] = lsum;
    __syncthreads();
    if (tid == 0) {
        float t = 0.f;
        for (int i = 0; i < 16; i++) t += red[i];
        g_losspart[blockIdx.x] = t;
    }
}

// ---------------- kernel 3: per-batch enc_batch via staged SMEM -----------
// z chunks staged coalesced into padded SMEM; inner accumulate is all-SMEM
// and conflict-free. Single-owner (k&3 == ks) -> no atomics, deterministic.
#define CHUNK 64
__global__ void __launch_bounds__(512, 1)
k_encbatch(const float* __restrict__ z) {
    extern __shared__ float sm[];
    float* sacc  = sm;                              // [256][128]   32768
    float* zs    = sm + KCODE * DCH;                // [128][65]     8320
    int*   ssidx = (int*)(zs + 128 * 65);           // [1024]
    int*   scnt  = ssidx + HW;                      // [256]
    const int tid = threadIdx.x, b = blockIdx.x;

    for (int i = tid; i < KCODE * DCH; i += 512) sacc[i] = 0.f;
    if (tid < 256) scnt[tid] = 0;
    for (int i = tid; i < HW; i += 512) ssidx[i] = g_idx[b * HW + i];

    const int ks = tid >> 7, c = tid & 127;
    const float* zb = z + (b * DCH) * HW;

    for (int ch = 0; ch < HW / CHUNK; ch++) {
        const int r0 = ch * CHUNK;
        __syncthreads();
        // stage: coalesced (consecutive threads -> consecutive rows)
        for (int i = tid; i < DCH * CHUNK; i += 512) {
            int cc = i >> 6, r = i & (CHUNK - 1);
            zs[cc * (CHUNK + 1) + r] = zb[cc * HW + r0 + r];
        }
        __syncthreads();
#pragma unroll 4
        for (int r = 0; r < CHUNK; r++) {
            int k = ssidx[r0 + r];
            if ((k & 3) == ks) {
                sacc[k * DCH + c] += zs[c * (CHUNK + 1) + r];
                if (c == 0) scnt[k]++;
            }
        }
    }
    __syncthreads();
    for (int i = tid; i < KCODE * DCH; i += 512)
        g_part[b * (KCODE * DCH) + i] = sacc[i];
    if (tid < 256) g_cntpart[b * KCODE + tid] = (float)scnt[tid];
}

// ---------------- kernel 4a: batch reduction stage A (16 batches) ---------
__global__ void k_reduceA() {
    int bg = blockIdx.x >> 8;          // 0..7
    int k  = blockIdx.x & 255;
    int c  = threadIdx.x;
    const float* p = g_part + (bg * 16) * (KCODE * DCH) + k * DCH + c;
    float s = 0.f;
#pragma unroll
    for (int bi = 0; bi < 16; bi++) s += p[bi * (KCODE * DCH)];
    g_part2[bg * (KCODE * DCH) + k * DCH + c] = s;
}

// ---------------- kernel 4b: stage B -> new_weight ------------------------
__global__ void k_reduceB(const float* __restrict__ emaw,
                          float* __restrict__ out) {
    int k = blockIdx.x, c = threadIdx.x;
    float s = 0.f;
#pragma unroll
    for (int bg = 0; bg < 8; bg++) s += g_part2[bg * (KCODE * DCH) + k * DCH + c];
    int i = k * DCH + c;
    out[NW_OFF + i] = __fadd_rn(__fmul_rn(0.99f, emaw[i]), __fmul_rn(0.01f, s));
}

// ---------------- kernel 5: counts, losses, snorm -------------------------
__global__ void k_final(const float* __restrict__ emac, float* __restrict__ out) {
    __shared__ float snc[256], sred[256];
    __shared__ float s_n;
    const int t = threadIdx.x;

    float cs = 0.f;
#pragma unroll 8
    for (int b = 0; b < BATCH; b++) cs += g_cntpart[b * KCODE + t];
    float nc = __fadd_rn(__fmul_rn(0.99f, emac[t]), __fmul_rn(0.01f, cs));
    out[CNT_OFF + t] = nc;
    snc[t] = nc;

    float lp = 0.f;
    for (int i = t; i < NTILES; i += 256) lp += g_losspart[i];
    sred[t] = lp;
    __syncthreads();

    if (t == 0) {
        float n = 0.f;
        for (int i = 0; i < 256; i++) n += snc[i];
        s_n = n;
        float L = 0.f;
        for (int i = 0; i < 256; i++) L += sred[i];
        L /= 16777216.0f;
        out[COMMIT_OFF] = 0.25f * L;
        out[CBL_OFF]    = L;
    }
    __syncthreads();

    float n = s_n;
    g_snorm[t] = __fmul_rn(__fdiv_rn(__fadd_rn(snc[t], 1e-5f),
                                     __fadd_rn(n, 256.0f * 1e-5f)), n);
}

// ---------------- kernel 6: new_codebook (parallel divisions) -------------
__global__ void k_ncb(float* __restrict__ out) {
    int k = blockIdx.x, c = threadIdx.x;
    int i = k * DCH + c;
    out[NCB_OFF + i] = __fdiv_rn(out[NW_OFF + i], g_snorm[k]);
}

// ---------------- launch ---------------------------------------------------
extern "C" void kernel_launch(void* const* d_in, const int* in_sizes, int n_in,
                              void* d_out, int out_size) {
    const float* z    = (const float*)d_in[0];
    const float* cb   = (const float*)d_in[1];
    const float* emac = (const float*)d_in[2];
    const float* emaw = (const float*)d_in[3];
    float* out = (float*)d_out;

    const int GEMM_SMEM = (16384 + 128 * SCB_STRIDE + 256 + 128) * 4;     // 199168
    const int ENC_SMEM  = (KCODE * DCH + 128 * 65) * 4 + (HW + KCODE) * 4; // 169472
    cudaFuncSetAttribute(k_gemm, cudaFuncAttributeMaxDynamicSharedMemorySize,
                         GEMM_SMEM);
    cudaFuncSetAttribute(k_encbatch, cudaFuncAttributeMaxDynamicSharedMemorySize,
                         ENC_SMEM);

    k_prep<<<1, 256>>>(cb);
    k_gemm<<<NTILES, 512, GEMM_SMEM>>>(z, cb, out);
    k_encbatch<<<BATCH, 512, ENC_SMEM>>>(z);
    k_reduceA<<<2048, 128>>>();
    k_reduceB<<<KCODE, DCH>>>(emaw, out);
    k_final<<<1, 256>>>(emac, out);
    k_ncb<<<KCODE, DCH>>>(out);
}